// round 14
// baseline (speedup 1.0000x reference)
#include <cuda_runtime.h>
#include <cuda_bf16.h>
#include <cuda_fp16.h>
#include <math.h>
#include <stdint.h>

#define BATCH 32
#define SEQT  512
#define IND   512
#define UNITS 1024
#define GDIM  4096              // 4*UNITS
#define MROWS (BATCH*SEQT)      // 16384

#define NS    4                 // K-split slices (recurrence)
#define KSL   256               // k per slice
#define NBLK  256               // 4 slices x 64 n-tiles (64 g each)
#define PITCH2 132              // u32 pitch for staged h rows (256k, ldmatrix-safe)
#define PX    36                // u32 pitch for xproj A staging (64k chunk)

// -------------------- device globals (no runtime alloc) --------------------
__device__ float         g_xg[(size_t)SEQT * BATCH * GDIM];   // [T][B][4U]
__device__ uint2         g_wfrag2[1u << 20];                  // Wh fp16 frags, 8MB
__device__ uint4         g_wxfrag[1u << 19];                  // Wx bf16 frags, 8MB
__device__ __nv_bfloat16 g_x_hi[(size_t)MROWS * IND];         // data split, 16MB
__device__ __nv_bfloat16 g_x_lo[(size_t)MROWS * IND];
__device__ __half        g_h[BATCH * UNITS];                  // h fp16 [b][k]
__device__ float         g_c[BATCH * UNITS];
__device__ float         g_part[(size_t)NS * BATCH * GDIM];   // [s][b][g], 2MB
__device__ unsigned int  g_bar_count;
__device__ unsigned int  g_bar_release;

// -------------------- helpers --------------------
__device__ __forceinline__ uint32_t smem_u32(const void* p) {
    uint32_t a;
    asm("{ .reg .u64 t; cvta.to.shared.u64 t, %1; cvt.u32.u64 %0, t; }"
        : "=r"(a) : "l"(p));
    return a;
}
__device__ __forceinline__ unsigned int bar_arrive_add(unsigned int* p) {
    unsigned int old;
    asm volatile("atom.add.release.gpu.global.u32 %0, [%1], 1;"
                 : "=r"(old) : "l"(p) : "memory");
    return old;
}
__device__ __forceinline__ void st_release(unsigned int* p, unsigned int v) {
    asm volatile("st.release.gpu.global.u32 [%0], %1;" :: "l"(p), "r"(v) : "memory");
}
__device__ __forceinline__ unsigned int ld_acquire(unsigned int* p) {
    unsigned int v;
    asm volatile("ld.acquire.gpu.global.u32 %0, [%1];" : "=r"(v) : "l"(p) : "memory");
    return v;
}
__device__ __forceinline__ void mma_bf16(float* d, const uint32_t* a,
                                         uint32_t b0, uint32_t b1) {
    asm volatile(
        "mma.sync.aligned.m16n8k16.row.col.f32.bf16.bf16.f32 "
        "{%0,%1,%2,%3}, {%4,%5,%6,%7}, {%8,%9}, {%0,%1,%2,%3};"
        : "+f"(d[0]), "+f"(d[1]), "+f"(d[2]), "+f"(d[3])
        : "r"(a[0]), "r"(a[1]), "r"(a[2]), "r"(a[3]), "r"(b0), "r"(b1));
}
__device__ __forceinline__ void mma_f16(float* d, const uint32_t* a,
                                        uint32_t b0, uint32_t b1) {
    asm volatile(
        "mma.sync.aligned.m16n8k16.row.col.f32.f16.f16.f32 "
        "{%0,%1,%2,%3}, {%4,%5,%6,%7}, {%8,%9}, {%0,%1,%2,%3};"
        : "+f"(d[0]), "+f"(d[1]), "+f"(d[2]), "+f"(d[3])
        : "r"(a[0]), "r"(a[1]), "r"(a[2]), "r"(a[3]), "r"(b0), "r"(b1));
}
__device__ __forceinline__ void ldmat4(uint32_t* r, uint32_t addr) {
    asm volatile("ldmatrix.sync.aligned.m8n8.x4.shared.b16 {%0,%1,%2,%3}, [%4];"
                 : "=r"(r[0]), "=r"(r[1]), "=r"(r[2]), "=r"(r[3]) : "r"(addr));
}
__device__ __forceinline__ uint32_t pack2(__nv_bfloat16 lo, __nv_bfloat16 hi) {
    uint16_t l = *(uint16_t*)&lo, h = *(uint16_t*)&hi;
    return ((uint32_t)h << 16) | l;
}
__device__ __forceinline__ uint32_t pack2h(__half lo, __half hi) {
    uint16_t l = *(uint16_t*)&lo, h = *(uint16_t*)&hi;
    return ((uint32_t)h << 16) | l;
}
__device__ __forceinline__ float fast_sigmoid(float x) {
    return __fdividef(1.0f, 1.0f + __expf(-x));
}
__device__ __forceinline__ float fast_tanh(float x) {
    return __fdividef(2.0f, 1.0f + __expf(-2.0f * x)) - 1.0f;
}

// ---------------------------------------------------------------------------
// init: h = 0, c = 1 (reference inits c to ones), reset barrier
// ---------------------------------------------------------------------------
__global__ void k_init_state() {
    int i = blockIdx.x * blockDim.x + threadIdx.x;
    if (i < BATCH * UNITS) {
        g_h[i] = __float2half(0.0f);
        g_c[i] = 1.0f;
    }
    if (i == 0) { g_bar_count = 0; g_bar_release = 0; }
}

// ---------------------------------------------------------------------------
// prep: split data into bf16 hi/lo (coalesced) — xproj path
// ---------------------------------------------------------------------------
__global__ void __launch_bounds__(256) k_prep_data(const float* __restrict__ data) {
    size_t i = (size_t)blockIdx.x * 256 + threadIdx.x;
    float x = data[i];
    __nv_bfloat16 hi = __float2bfloat16(x);
    g_x_hi[i] = hi;
    g_x_lo[i] = __float2bfloat16(x - __bfloat162float(hi));
}

// ---------------------------------------------------------------------------
// prep: Wh -> fp16 fragment pairs, NS=4 / 64-col tile layout.
// q bits: s(2) nt(6) w(3) ks(4) lane(5)
//   col = nt*64 + w*8 + lane/4
//   k   = s*256 + ks*16 + 2*(lane&3)   (j0: k,k+1; j1: k+8,k+9)
// ---------------------------------------------------------------------------
__global__ void __launch_bounds__(256) k_prep_frag(const float* __restrict__ Wh) {
    uint32_t q = blockIdx.x * 256 + threadIdx.x;   // 0 .. 2^20-1
    int lane = q & 31;
    int ks   = (q >> 5) & 15;
    int w    = (q >> 9) & 7;
    int nt   = (q >> 12) & 63;
    int s    = (q >> 18) & 3;

    int col = nt * 64 + w * 8 + (lane >> 2);
    int k   = s * KSL + ks * 16 + 2 * (lane & 3);

    float x0 = __ldg(&Wh[(size_t)k * GDIM + col]);
    float x1 = __ldg(&Wh[(size_t)(k + 1) * GDIM + col]);
    float x2 = __ldg(&Wh[(size_t)(k + 8) * GDIM + col]);
    float x3 = __ldg(&Wh[(size_t)(k + 9) * GDIM + col]);

    uint2 v;
    v.x = pack2h(__float2half(x0), __float2half(x1));
    v.y = pack2h(__float2half(x2), __float2half(x3));
    g_wfrag2[q] = v;
}

// ---------------------------------------------------------------------------
// prep: Wx -> packed bf16 uint4 fragments (validated, unchanged)
// ---------------------------------------------------------------------------
__global__ void __launch_bounds__(256) k_prep_wx(const float* __restrict__ Wx) {
    uint32_t q = blockIdx.x * 256 + threadIdx.x;   // 0 .. 2^19-1
    int lane = q & 31;
    int ks   = (q >> 5) & 31;
    int nf   = (q >> 10) & 7;
    int wn   = (q >> 13) & 1;
    int nt0  = (q >> 14) & 31;

    int col = nt0 * 128 + wn * 64 + nf * 8 + (lane >> 2);
    int k   = ks * 16 + 2 * (lane & 3);

    float x0 = __ldg(&Wx[(size_t)k * GDIM + col]);
    float x1 = __ldg(&Wx[(size_t)(k + 1) * GDIM + col]);
    float x2 = __ldg(&Wx[(size_t)(k + 8) * GDIM + col]);
    float x3 = __ldg(&Wx[(size_t)(k + 9) * GDIM + col]);

    __nv_bfloat16 h0 = __float2bfloat16(x0), h1 = __float2bfloat16(x1);
    __nv_bfloat16 h2 = __float2bfloat16(x2), h3 = __float2bfloat16(x3);
    __nv_bfloat16 l0 = __float2bfloat16(x0 - __bfloat162float(h0));
    __nv_bfloat16 l1 = __float2bfloat16(x1 - __bfloat162float(h1));
    __nv_bfloat16 l2 = __float2bfloat16(x2 - __bfloat162float(h2));
    __nv_bfloat16 l3 = __float2bfloat16(x3 - __bfloat162float(h3));

    uint4 v;
    v.x = pack2(h0, h1);
    v.y = pack2(h2, h3);
    v.z = pack2(l0, l1);
    v.w = pack2(l2, l3);
    g_wxfrag[q] = v;
}

// ---------------------------------------------------------------------------
// x-projection on tensor cores (unchanged from R10 — validated, bf16 3-term).
// ---------------------------------------------------------------------------
__global__ void __launch_bounds__(256, 2) k_xproj_mma(const float* __restrict__ bias,
                                                      float* __restrict__ dummy) {
    __shared__ uint32_t sh[2][128][PX];

    int tid = threadIdx.x;
    int w = tid >> 5, lane = tid & 31;
    int wn = w & 1, wm = w >> 1;
    int nt0 = blockIdx.x;
    int mt0 = blockIdx.y;
    int n0 = nt0 * 128;
    size_t m0 = (size_t)mt0 * 128;

    const uint32_t* xh = (const uint32_t*)g_x_hi;
    const uint32_t* xl = (const uint32_t*)g_x_lo;
    const uint4* wbx = g_wxfrag + ((size_t)(nt0 * 2 + wn) * 8) * 1024;

    float acc[2][8][4];
#pragma unroll
    for (int mf = 0; mf < 2; mf++)
#pragma unroll
        for (int nf = 0; nf < 8; nf++)
#pragma unroll
            for (int e = 0; e < 4; e++) acc[mf][nf][e] = 0.0f;

    uint32_t sb0 = smem_u32(&sh[0][0][0]);
    uint32_t sb1 = smem_u32(&sh[1][0][0]);
    int lrow = lane & 15, lhalf = lane >> 4;

    int srow = tid >> 1, sseg = tid & 1;

#pragma unroll 1
    for (int chunk = 0; chunk < 8; chunk++) {
        {
            const uint4* ph = (const uint4*)(xh + (m0 + srow) * 256 + chunk * 32 + sseg * 16);
            const uint4* pl = (const uint4*)(xl + (m0 + srow) * 256 + chunk * 32 + sseg * 16);
#pragma unroll
            for (int j = 0; j < 4; j++)
                *(uint4*)&sh[0][srow][sseg * 16 + j * 4] = ph[j];
#pragma unroll
            for (int j = 0; j < 4; j++)
                *(uint4*)&sh[1][srow][sseg * 16 + j * 4] = pl[j];
        }
        __syncthreads();

#pragma unroll
        for (int ks4 = 0; ks4 < 4; ks4++) {
            int ks = chunk * 4 + ks4;
            uint4 bv[8];
#pragma unroll
            for (int nf = 0; nf < 8; nf++)
                bv[nf] = wbx[(size_t)nf * 1024 + ks * 32 + lane];
#pragma unroll
            for (int mf = 0; mf < 2; mf++) {
                int row = wm * 32 + mf * 16 + lrow;
                uint32_t off = ((uint32_t)row * PX + ks4 * 8 + lhalf * 4) * 4;
                uint32_t ah[4], al[4];
                ldmat4(ah, sb0 + off);
                ldmat4(al, sb1 + off);
#pragma unroll
                for (int nf = 0; nf < 8; nf++) {
                    mma_bf16(acc[mf][nf], ah, bv[nf].x, bv[nf].y);
                    mma_bf16(acc[mf][nf], ah, bv[nf].z, bv[nf].w);
                    mma_bf16(acc[mf][nf], al, bv[nf].x, bv[nf].y);
                }
            }
        }
        __syncthreads();
    }

    int b  = (int)(m0 >> 9);
    int t0 = (int)(m0 & 511);
    int c2 = (lane & 3) * 2;
#pragma unroll
    for (int nf = 0; nf < 8; nf++) {
        int col = n0 + wn * 64 + nf * 8 + c2;
        float2 bb = *(const float2*)&bias[col];
#pragma unroll
        for (int mf = 0; mf < 2; mf++) {
            int r0 = t0 + wm * 32 + mf * 16 + (lane >> 2);
            float2 v0 = {acc[mf][nf][0] + bb.x, acc[mf][nf][1] + bb.y};
            float2 v1 = {acc[mf][nf][2] + bb.x, acc[mf][nf][3] + bb.y};
            *(float2*)&g_xg[((size_t)r0 * BATCH + b) * GDIM + col] = v0;
            *(float2*)&g_xg[((size_t)(r0 + 8) * BATCH + b) * GDIM + col] = v1;
        }
    }
    (void)dummy;
}

// ---------------------------------------------------------------------------
// Fused LSTM step (fp16 1-term, NS=4 x 64-col tiles):
//   grid = 256 blocks (4 slices x 64 n-tiles) x 256 threads, 3 CTAs/SM.
//   Warp w owns 8 cols x 32 b x 256 k: 16 ks x 2 MMA.
// ---------------------------------------------------------------------------
__global__ void __launch_bounds__(256, 3) k_step(int t, float* __restrict__ out) {
    __shared__ uint32_t sh[BATCH][PITCH2];      // 16.9KB

    int tid = threadIdx.x;
    int w = tid >> 5, lane = tid & 31;
    int bx = blockIdx.x;
    int s   = bx >> 6;          // slice 0..3
    int nt0 = bx & 63;          // g-tile (64 wide)

    const uint32_t* hh = (const uint32_t*)g_h;
    const uint2* wb = g_wfrag2 + ((size_t)((s * 64 + nt0) * 8 + w)) * 512;
    //   + ks*32 + lane

    // ---- stage h slice into SMEM (coalesced): 32 rows x 128 u32 ----
    {
        int b = tid >> 3, seg = tid & 7;   // 8 threads/row, 16 u32 each
        const uint4* ph = (const uint4*)(hh + (size_t)b * 512 + s * 128 + seg * 16);
        uint4 v0 = ph[0], v1 = ph[1], v2 = ph[2], v3 = ph[3];
        *(uint4*)&sh[b][seg * 16]      = v0;
        *(uint4*)&sh[b][seg * 16 + 4]  = v1;
        *(uint4*)&sh[b][seg * 16 + 8]  = v2;
        *(uint4*)&sh[b][seg * 16 + 12] = v3;
    }
    __syncthreads();

    float acc[2][4];
#pragma unroll
    for (int m = 0; m < 2; m++)
#pragma unroll
        for (int e = 0; e < 4; e++) acc[m][e] = 0.0f;

    uint32_t sb0 = smem_u32(&sh[0][0]);
    int lrow = lane & 15, lhalf = lane >> 4;

    uint2 bcur = wb[lane];

#pragma unroll
    for (int ks = 0; ks < 16; ks++) {
        uint2 bnxt;
        if (ks < 15) bnxt = wb[(ks + 1) * 32 + lane];
        uint32_t ah[2][4];
#pragma unroll
        for (int m = 0; m < 2; m++) {
            uint32_t off = (((uint32_t)(m * 16 + lrow)) * PITCH2
                            + ks * 8 + lhalf * 4) * 4;
            ldmat4(ah[m], sb0 + off);
        }
        mma_f16(acc[0], ah[0], bcur.x, bcur.y);
        mma_f16(acc[1], ah[1], bcur.x, bcur.y);
        bcur = bnxt;
    }

    // store partials: g_part[s][b][g]
    {
        int r = lane >> 2, c2 = (lane & 3) * 2;
        int col = nt0 * 64 + w * 8 + c2;
        float* pp = g_part + ((size_t)s * BATCH) * GDIM;
#pragma unroll
        for (int m = 0; m < 2; m++) {
            int b0 = m * 16 + r;
            float2 v0 = {acc[m][0], acc[m][1]};
            float2 v1 = {acc[m][2], acc[m][3]};
            *(float2*)&pp[(size_t)b0 * GDIM + col] = v0;
            *(float2*)&pp[(size_t)(b0 + 8) * GDIM + col] = v1;
        }
    }

    // ---- prefetch xg (barrier-independent) ----
    int pidx = bx * 128 + (tid & 127);
    int pb = pidx >> 10;
    int pu = pidx & 1023;
    const float* xg = g_xg + ((size_t)t * BATCH + pb) * GDIM;
    float ai = 0.f, af = 0.f, ag = 0.f, ao = 0.f;
    if (tid < 128) {
        ai = xg[pu];
        af = xg[UNITS + pu];
        ag = xg[2 * UNITS + pu];
        ao = xg[3 * UNITS + pu];
    }

    // ---- grid barrier ----
    __syncthreads();
    if (tid == 0) {
        unsigned int old = bar_arrive_add(&g_bar_count);
        if (old == NBLK - 1) {
            g_bar_count = 0;
            st_release(&g_bar_release, (unsigned int)(t + 1));
        } else {
            while (ld_acquire(&g_bar_release) < (unsigned int)(t + 1))
                __nanosleep(32);
        }
    }
    __syncthreads();

    // ---- phase 2: pointwise, 128 elements per block ----
    if (tid < 128) {
#pragma unroll
        for (int ss = 0; ss < NS; ss++) {
            const float* p = g_part + ((size_t)ss * BATCH + pb) * GDIM;
            ai += p[pu];
            af += p[UNITS + pu];
            ag += p[2 * UNITS + pu];
            ao += p[3 * UNITS + pu];
        }

        float ig = fast_sigmoid(ai);
        float fg = fast_sigmoid(af);
        float gg = fast_tanh(ag);
        float og = fast_sigmoid(ao);

        int cu = pb * UNITS + pu;
        float c = fg * g_c[cu] + ig * gg;
        g_c[cu] = c;
        float h = og * fast_tanh(c);

        out[((size_t)pb * SEQT + t) * UNITS + pu] = h;
        g_h[cu] = __float2half(h);
    }
}

// ---------------------------------------------------------------------------
// kernel_launch: 517 graph nodes.
// ---------------------------------------------------------------------------
extern "C" void kernel_launch(void* const* d_in, const int* in_sizes, int n_in,
                              void* d_out, int out_size) {
    (void)in_sizes; (void)n_in; (void)out_size;
    const float* data = (const float*)d_in[0];   // [32,512,512]
    const float* Wx   = (const float*)d_in[1];   // [512,4096]
    const float* Wh   = (const float*)d_in[2];   // [1024,4096]
    const float* bias = (const float*)d_in[3];   // [4096]
    float* out = (float*)d_out;                  // [32,512,1024]

    k_init_state<<<(BATCH * UNITS + 255) / 256, 256>>>();
    k_prep_data<<<(int)(((size_t)MROWS * IND) / 256), 256>>>(data);
    k_prep_frag<<<4096, 256>>>(Wh);
    k_prep_wx<<<2048, 256>>>(Wx);
    k_xproj_mma<<<dim3(32, 128), 256>>>(bias, out);

    for (int t = 0; t < SEQT; t++)
        k_step<<<NBLK, 256>>>(t, out);
}

// round 15
// speedup vs baseline: 1.1006x; 1.1006x over previous
#include <cuda_runtime.h>
#include <cuda_bf16.h>
#include <cuda_fp16.h>
#include <math.h>
#include <stdint.h>

#define BATCH 32
#define SEQT  512
#define IND   512
#define UNITS 1024
#define GDIM  4096              // 4*UNITS
#define MROWS (BATCH*SEQT)      // 16384

#define NS    8                 // K-split slices (recurrence)
#define KSL   (UNITS/NS)        // 128 k per slice
#define NBLK  256               // 8 slices x 32 n-tiles (128 g each)
#define PITCH 76                // u32 pitch for staged h rows (ldmatrix-friendly)
#define PX    36                // u32 pitch for xproj A staging (64k chunk)

// -------------------- device globals (no runtime alloc) --------------------
__device__ float         g_xg[(size_t)SEQT * BATCH * GDIM];   // [T][B][4U]
__device__ uint2         g_wfrag2[1u << 20];                  // Wh fp16 frags, 8MB
__device__ uint4         g_wxfrag[1u << 19];                  // Wx bf16 frags, 8MB
__device__ __nv_bfloat16 g_x_hi[(size_t)MROWS * IND];         // data split, 16MB
__device__ __nv_bfloat16 g_x_lo[(size_t)MROWS * IND];
__device__ __half        g_h[BATCH * UNITS];                  // h fp16 [b][k]
__device__ float         g_c[BATCH * UNITS];
__device__ float         g_part[(size_t)NS * BATCH * GDIM];   // [s][b][g], 4MB
__device__ unsigned int  g_bar_count;
__device__ unsigned int  g_bar_release;

// -------------------- helpers --------------------
__device__ __forceinline__ uint32_t smem_u32(const void* p) {
    uint32_t a;
    asm("{ .reg .u64 t; cvta.to.shared.u64 t, %1; cvt.u32.u64 %0, t; }"
        : "=r"(a) : "l"(p));
    return a;
}
__device__ __forceinline__ unsigned int bar_arrive_add(unsigned int* p) {
    unsigned int old;
    asm volatile("atom.add.release.gpu.global.u32 %0, [%1], 1;"
                 : "=r"(old) : "l"(p) : "memory");
    return old;
}
__device__ __forceinline__ void st_release(unsigned int* p, unsigned int v) {
    asm volatile("st.release.gpu.global.u32 [%0], %1;" :: "l"(p), "r"(v) : "memory");
}
__device__ __forceinline__ unsigned int ld_acquire(unsigned int* p) {
    unsigned int v;
    asm volatile("ld.acquire.gpu.global.u32 %0, [%1];" : "=r"(v) : "l"(p) : "memory");
    return v;
}
__device__ __forceinline__ void mma_bf16(float* d, const uint32_t* a,
                                         uint32_t b0, uint32_t b1) {
    asm volatile(
        "mma.sync.aligned.m16n8k16.row.col.f32.bf16.bf16.f32 "
        "{%0,%1,%2,%3}, {%4,%5,%6,%7}, {%8,%9}, {%0,%1,%2,%3};"
        : "+f"(d[0]), "+f"(d[1]), "+f"(d[2]), "+f"(d[3])
        : "r"(a[0]), "r"(a[1]), "r"(a[2]), "r"(a[3]), "r"(b0), "r"(b1));
}
__device__ __forceinline__ void mma_f16(float* d, const uint32_t* a,
                                        uint32_t b0, uint32_t b1) {
    asm volatile(
        "mma.sync.aligned.m16n8k16.row.col.f32.f16.f16.f32 "
        "{%0,%1,%2,%3}, {%4,%5,%6,%7}, {%8,%9}, {%0,%1,%2,%3};"
        : "+f"(d[0]), "+f"(d[1]), "+f"(d[2]), "+f"(d[3])
        : "r"(a[0]), "r"(a[1]), "r"(a[2]), "r"(a[3]), "r"(b0), "r"(b1));
}
__device__ __forceinline__ void ldmat4(uint32_t* r, uint32_t addr) {
    asm volatile("ldmatrix.sync.aligned.m8n8.x4.shared.b16 {%0,%1,%2,%3}, [%4];"
                 : "=r"(r[0]), "=r"(r[1]), "=r"(r[2]), "=r"(r[3]) : "r"(addr));
}
__device__ __forceinline__ uint32_t pack2(__nv_bfloat16 lo, __nv_bfloat16 hi) {
    uint16_t l = *(uint16_t*)&lo, h = *(uint16_t*)&hi;
    return ((uint32_t)h << 16) | l;
}
__device__ __forceinline__ uint32_t pack2h(__half lo, __half hi) {
    uint16_t l = *(uint16_t*)&lo, h = *(uint16_t*)&hi;
    return ((uint32_t)h << 16) | l;
}
__device__ __forceinline__ float fast_sigmoid(float x) {
    return __fdividef(1.0f, 1.0f + __expf(-x));
}
__device__ __forceinline__ float fast_tanh(float x) {
    return __fdividef(2.0f, 1.0f + __expf(-2.0f * x)) - 1.0f;
}

// ---------------------------------------------------------------------------
// init: h = 0, c = 1 (reference inits c to ones), reset barrier
// ---------------------------------------------------------------------------
__global__ void k_init_state() {
    int i = blockIdx.x * blockDim.x + threadIdx.x;
    if (i < BATCH * UNITS) {
        g_h[i] = __float2half(0.0f);
        g_c[i] = 1.0f;
    }
    if (i == 0) { g_bar_count = 0; g_bar_release = 0; }
}

// ---------------------------------------------------------------------------
// prep: split data into bf16 hi/lo (coalesced) — xproj path
// ---------------------------------------------------------------------------
__global__ void __launch_bounds__(256) k_prep_data(const float* __restrict__ data) {
    size_t i = (size_t)blockIdx.x * 256 + threadIdx.x;
    float x = data[i];
    __nv_bfloat16 hi = __float2bfloat16(x);
    g_x_hi[i] = hi;
    g_x_lo[i] = __float2bfloat16(x - __bfloat162float(hi));
}

// ---------------------------------------------------------------------------
// prep: Wh -> fp16 fragment pairs (R13 layout, validated)
// q bits: s(3) nt0(5) w(3) ntl(1) ks(3) lane(5)
//   col = nt0*128 + w*16 + ntl*8 + lane/4
//   k   = s*128 + ks*16 + 2*(lane&3)   (j0: k,k+1; j1: k+8,k+9)
// ---------------------------------------------------------------------------
__global__ void __launch_bounds__(256) k_prep_frag(const float* __restrict__ Wh) {
    uint32_t q = blockIdx.x * 256 + threadIdx.x;   // 0 .. 2^20-1
    int lane = q & 31;
    int ks   = (q >> 5) & 7;
    int ntl  = (q >> 8) & 1;
    int w    = (q >> 9) & 7;
    int nt0  = (q >> 12) & 31;
    int s    = (q >> 17) & 7;

    int col = nt0 * 128 + w * 16 + ntl * 8 + (lane >> 2);
    int k   = s * KSL + ks * 16 + 2 * (lane & 3);

    float x0 = __ldg(&Wh[(size_t)k * GDIM + col]);
    float x1 = __ldg(&Wh[(size_t)(k + 1) * GDIM + col]);
    float x2 = __ldg(&Wh[(size_t)(k + 8) * GDIM + col]);
    float x3 = __ldg(&Wh[(size_t)(k + 9) * GDIM + col]);

    uint2 v;
    v.x = pack2h(__float2half(x0), __float2half(x1));
    v.y = pack2h(__float2half(x2), __float2half(x3));
    g_wfrag2[q] = v;
}

// ---------------------------------------------------------------------------
// prep: Wx -> packed bf16 uint4 fragments (validated, unchanged)
// ---------------------------------------------------------------------------
__global__ void __launch_bounds__(256) k_prep_wx(const float* __restrict__ Wx) {
    uint32_t q = blockIdx.x * 256 + threadIdx.x;   // 0 .. 2^19-1
    int lane = q & 31;
    int ks   = (q >> 5) & 31;
    int nf   = (q >> 10) & 7;
    int wn   = (q >> 13) & 1;
    int nt0  = (q >> 14) & 31;

    int col = nt0 * 128 + wn * 64 + nf * 8 + (lane >> 2);
    int k   = ks * 16 + 2 * (lane & 3);

    float x0 = __ldg(&Wx[(size_t)k * GDIM + col]);
    float x1 = __ldg(&Wx[(size_t)(k + 1) * GDIM + col]);
    float x2 = __ldg(&Wx[(size_t)(k + 8) * GDIM + col]);
    float x3 = __ldg(&Wx[(size_t)(k + 9) * GDIM + col]);

    __nv_bfloat16 h0 = __float2bfloat16(x0), h1 = __float2bfloat16(x1);
    __nv_bfloat16 h2 = __float2bfloat16(x2), h3 = __float2bfloat16(x3);
    __nv_bfloat16 l0 = __float2bfloat16(x0 - __bfloat162float(h0));
    __nv_bfloat16 l1 = __float2bfloat16(x1 - __bfloat162float(h1));
    __nv_bfloat16 l2 = __float2bfloat16(x2 - __bfloat162float(h2));
    __nv_bfloat16 l3 = __float2bfloat16(x3 - __bfloat162float(h3));

    uint4 v;
    v.x = pack2(h0, h1);
    v.y = pack2(h2, h3);
    v.z = pack2(l0, l1);
    v.w = pack2(l2, l3);
    g_wxfrag[q] = v;
}

// ---------------------------------------------------------------------------
// x-projection on tensor cores (unchanged from R10 — validated, bf16 3-term).
// ---------------------------------------------------------------------------
__global__ void __launch_bounds__(256, 2) k_xproj_mma(const float* __restrict__ bias,
                                                      float* __restrict__ dummy) {
    __shared__ uint32_t sh[2][128][PX];

    int tid = threadIdx.x;
    int w = tid >> 5, lane = tid & 31;
    int wn = w & 1, wm = w >> 1;
    int nt0 = blockIdx.x;
    int mt0 = blockIdx.y;
    int n0 = nt0 * 128;
    size_t m0 = (size_t)mt0 * 128;

    const uint32_t* xh = (const uint32_t*)g_x_hi;
    const uint32_t* xl = (const uint32_t*)g_x_lo;
    const uint4* wbx = g_wxfrag + ((size_t)(nt0 * 2 + wn) * 8) * 1024;

    float acc[2][8][4];
#pragma unroll
    for (int mf = 0; mf < 2; mf++)
#pragma unroll
        for (int nf = 0; nf < 8; nf++)
#pragma unroll
            for (int e = 0; e < 4; e++) acc[mf][nf][e] = 0.0f;

    uint32_t sb0 = smem_u32(&sh[0][0][0]);
    uint32_t sb1 = smem_u32(&sh[1][0][0]);
    int lrow = lane & 15, lhalf = lane >> 4;

    int srow = tid >> 1, sseg = tid & 1;

#pragma unroll 1
    for (int chunk = 0; chunk < 8; chunk++) {
        {
            const uint4* ph = (const uint4*)(xh + (m0 + srow) * 256 + chunk * 32 + sseg * 16);
            const uint4* pl = (const uint4*)(xl + (m0 + srow) * 256 + chunk * 32 + sseg * 16);
#pragma unroll
            for (int j = 0; j < 4; j++)
                *(uint4*)&sh[0][srow][sseg * 16 + j * 4] = ph[j];
#pragma unroll
            for (int j = 0; j < 4; j++)
                *(uint4*)&sh[1][srow][sseg * 16 + j * 4] = pl[j];
        }
        __syncthreads();

#pragma unroll
        for (int ks4 = 0; ks4 < 4; ks4++) {
            int ks = chunk * 4 + ks4;
            uint4 bv[8];
#pragma unroll
            for (int nf = 0; nf < 8; nf++)
                bv[nf] = wbx[(size_t)nf * 1024 + ks * 32 + lane];
#pragma unroll
            for (int mf = 0; mf < 2; mf++) {
                int row = wm * 32 + mf * 16 + lrow;
                uint32_t off = ((uint32_t)row * PX + ks4 * 8 + lhalf * 4) * 4;
                uint32_t ah[4], al[4];
                ldmat4(ah, sb0 + off);
                ldmat4(al, sb1 + off);
#pragma unroll
                for (int nf = 0; nf < 8; nf++) {
                    mma_bf16(acc[mf][nf], ah, bv[nf].x, bv[nf].y);
                    mma_bf16(acc[mf][nf], ah, bv[nf].z, bv[nf].w);
                    mma_bf16(acc[mf][nf], al, bv[nf].x, bv[nf].y);
                }
            }
        }
        __syncthreads();
    }

    int b  = (int)(m0 >> 9);
    int t0 = (int)(m0 & 511);
    int c2 = (lane & 3) * 2;
#pragma unroll
    for (int nf = 0; nf < 8; nf++) {
        int col = n0 + wn * 64 + nf * 8 + c2;
        float2 bb = *(const float2*)&bias[col];
#pragma unroll
        for (int mf = 0; mf < 2; mf++) {
            int r0 = t0 + wm * 32 + mf * 16 + (lane >> 2);
            float2 v0 = {acc[mf][nf][0] + bb.x, acc[mf][nf][1] + bb.y};
            float2 v1 = {acc[mf][nf][2] + bb.x, acc[mf][nf][3] + bb.y};
            *(float2*)&g_xg[((size_t)r0 * BATCH + b) * GDIM + col] = v0;
            *(float2*)&g_xg[((size_t)(r0 + 8) * BATCH + b) * GDIM + col] = v1;
        }
    }
    (void)dummy;
}

// ---------------------------------------------------------------------------
// Fused LSTM step (R13 structure: fp16 1-term, NS=8, dual B streams)
// + fast MUFU gates. grid = 256 blocks x 256 threads, 3 CTAs/SM.
// ---------------------------------------------------------------------------
__global__ void __launch_bounds__(256, 3) k_step(int t, float* __restrict__ out) {
    __shared__ uint32_t sh[BATCH][PITCH];

    int tid = threadIdx.x;
    int w = tid >> 5, lane = tid & 31;
    int bx = blockIdx.x;
    int s   = bx >> 5;
    int nt0 = bx & 31;

    const uint32_t* hh = (const uint32_t*)g_h;
    const uint2* wb = g_wfrag2 + ((((size_t)(s * 32 + nt0)) * 8 + w) * 2) * 256;

    // ---- stage h slice into SMEM (coalesced, single term) ----
    {
        int b = tid >> 3, seg = tid & 7;   // 8 threads/row, 8 u32 each
        const uint4* ph = (const uint4*)(hh + (size_t)b * 512 + s * 64 + seg * 8);
        uint4 v0 = ph[0], v1 = ph[1];
        *(uint4*)&sh[b][seg * 8]     = v0;
        *(uint4*)&sh[b][seg * 8 + 4] = v1;
    }
    __syncthreads();

    float acc[2][2][4];
#pragma unroll
    for (int m = 0; m < 2; m++)
#pragma unroll
        for (int n = 0; n < 2; n++)
#pragma unroll
            for (int e = 0; e < 4; e++) acc[m][n][e] = 0.0f;

    uint32_t sb0 = smem_u32(&sh[0][0]);
    int lrow = lane & 15, lhalf = lane >> 4;

    uint2 bcur0 = wb[lane];
    uint2 bcur1 = wb[256 + lane];

#pragma unroll
    for (int ks = 0; ks < 8; ks++) {
        uint2 bnxt0, bnxt1;
        if (ks < 7) {
            bnxt0 = wb[(ks + 1) * 32 + lane];
            bnxt1 = wb[256 + (ks + 1) * 32 + lane];
        }
        uint32_t ah[2][4];
#pragma unroll
        for (int m = 0; m < 2; m++) {
            uint32_t off = (((uint32_t)(m * 16 + lrow)) * PITCH
                            + ks * 8 + lhalf * 4) * 4;
            ldmat4(ah[m], sb0 + off);
        }
#pragma unroll
        for (int m = 0; m < 2; m++) {
            mma_f16(acc[m][0], ah[m], bcur0.x, bcur0.y);
            mma_f16(acc[m][1], ah[m], bcur1.x, bcur1.y);
        }
        bcur0 = bnxt0;
        bcur1 = bnxt1;
    }

    // store partials: g_part[s][b][g]
    {
        int r = lane >> 2, c2 = (lane & 3) * 2;
        float* pp = g_part + ((size_t)s * BATCH) * GDIM;
#pragma unroll
        for (int m = 0; m < 2; m++) {
            int b0 = m * 16 + r;
#pragma unroll
            for (int n = 0; n < 2; n++) {
                int col = nt0 * 128 + w * 16 + n * 8 + c2;
                float2 v0 = {acc[m][n][0], acc[m][n][1]};
                float2 v1 = {acc[m][n][2], acc[m][n][3]};
                *(float2*)&pp[(size_t)b0 * GDIM + col] = v0;
                *(float2*)&pp[(size_t)(b0 + 8) * GDIM + col] = v1;
            }
        }
    }

    // ---- prefetch xg (barrier-independent) ----
    int pidx = bx * 128 + (tid & 127);
    int pb = pidx >> 10;
    int pu = pidx & 1023;
    const float* xg = g_xg + ((size_t)t * BATCH + pb) * GDIM;
    float ai = 0.f, af = 0.f, ag = 0.f, ao = 0.f;
    if (tid < 128) {
        ai = xg[pu];
        af = xg[UNITS + pu];
        ag = xg[2 * UNITS + pu];
        ao = xg[3 * UNITS + pu];
    }

    // ---- grid barrier ----
    __syncthreads();
    if (tid == 0) {
        unsigned int old = bar_arrive_add(&g_bar_count);
        if (old == NBLK - 1) {
            g_bar_count = 0;
            st_release(&g_bar_release, (unsigned int)(t + 1));
        } else {
            while (ld_acquire(&g_bar_release) < (unsigned int)(t + 1))
                __nanosleep(32);
        }
    }
    __syncthreads();

    // ---- phase 2: pointwise, 128 elements per block ----
    if (tid < 128) {
#pragma unroll
        for (int ss = 0; ss < NS; ss++) {
            const float* p = g_part + ((size_t)ss * BATCH + pb) * GDIM;
            ai += p[pu];
            af += p[UNITS + pu];
            ag += p[2 * UNITS + pu];
            ao += p[3 * UNITS + pu];
        }

        float ig = fast_sigmoid(ai);
        float fg = fast_sigmoid(af);
        float gg = fast_tanh(ag);
        float og = fast_sigmoid(ao);

        int cu = pb * UNITS + pu;
        float c = fg * g_c[cu] + ig * gg;
        g_c[cu] = c;
        float h = og * fast_tanh(c);

        out[((size_t)pb * SEQT + t) * UNITS + pu] = h;
        g_h[cu] = __float2half(h);
    }
}

// ---------------------------------------------------------------------------
// kernel_launch: 517 graph nodes.
// ---------------------------------------------------------------------------
extern "C" void kernel_launch(void* const* d_in, const int* in_sizes, int n_in,
                              void* d_out, int out_size) {
    (void)in_sizes; (void)n_in; (void)out_size;
    const float* data = (const float*)d_in[0];   // [32,512,512]
    const float* Wx   = (const float*)d_in[1];   // [512,4096]
    const float* Wh   = (const float*)d_in[2];   // [1024,4096]
    const float* bias = (const float*)d_in[3];   // [4096]
    float* out = (float*)d_out;                  // [32,512,1024]

    k_init_state<<<(BATCH * UNITS + 255) / 256, 256>>>();
    k_prep_data<<<(int)(((size_t)MROWS * IND) / 256), 256>>>(data);
    k_prep_frag<<<4096, 256>>>(Wh);
    k_prep_wx<<<2048, 256>>>(Wx);
    k_xproj_mma<<<dim3(32, 128), 256>>>(bias, out);

    for (int t = 0; t < SEQT; t++)
        k_step<<<NBLK, 256>>>(t, out);
}

// round 16
// speedup vs baseline: 1.1402x; 1.0360x over previous
#include <cuda_runtime.h>
#include <cuda_bf16.h>
#include <cuda_fp16.h>
#include <math.h>
#include <stdint.h>

#define BATCH 32
#define SEQT  512
#define IND   512
#define UNITS 1024
#define GDIM  4096              // 4*UNITS
#define MROWS (BATCH*SEQT)      // 16384

#define NS    8                 // K-split slices (recurrence)
#define KSL   (UNITS/NS)        // 128 k per slice
#define NBLK  256               // 8 slices x 32 n-tiles (128 g each)
#define PITCH 76                // u32 pitch for staged h rows (ldmatrix-friendly)
#define PX    36                // u32 pitch for xproj A staging (64k chunk)

// -------------------- device globals (no runtime alloc) --------------------
__device__ float         g_xg[(size_t)SEQT * BATCH * GDIM];   // [T][B][4U]
__device__ uint2         g_wfrag2[1u << 20];                  // Wh fp16 frags, 8MB
__device__ uint2         g_wxfrag2[1u << 19];                 // Wx fp16 frags, 4MB
__device__ __half        g_x_hi[(size_t)MROWS * IND];         // data fp16 split, 16MB
__device__ __half        g_x_lo[(size_t)MROWS * IND];
__device__ __half        g_h[BATCH * UNITS];                  // h fp16 [b][k]
__device__ float         g_c[BATCH * UNITS];
__device__ float         g_part[(size_t)NS * BATCH * GDIM];   // [s][b][g], 4MB
__device__ unsigned int  g_bar_count;
__device__ unsigned int  g_bar_release;

// -------------------- helpers --------------------
__device__ __forceinline__ uint32_t smem_u32(const void* p) {
    uint32_t a;
    asm("{ .reg .u64 t; cvta.to.shared.u64 t, %1; cvt.u32.u64 %0, t; }"
        : "=r"(a) : "l"(p));
    return a;
}
__device__ __forceinline__ unsigned int bar_arrive_add(unsigned int* p) {
    unsigned int old;
    asm volatile("atom.add.release.gpu.global.u32 %0, [%1], 1;"
                 : "=r"(old) : "l"(p) : "memory");
    return old;
}
__device__ __forceinline__ void st_release(unsigned int* p, unsigned int v) {
    asm volatile("st.release.gpu.global.u32 [%0], %1;" :: "l"(p), "r"(v) : "memory");
}
__device__ __forceinline__ unsigned int ld_acquire(unsigned int* p) {
    unsigned int v;
    asm volatile("ld.acquire.gpu.global.u32 %0, [%1];" : "=r"(v) : "l"(p) : "memory");
    return v;
}
__device__ __forceinline__ void mma_f16(float* d, const uint32_t* a,
                                        uint32_t b0, uint32_t b1) {
    asm volatile(
        "mma.sync.aligned.m16n8k16.row.col.f32.f16.f16.f32 "
        "{%0,%1,%2,%3}, {%4,%5,%6,%7}, {%8,%9}, {%0,%1,%2,%3};"
        : "+f"(d[0]), "+f"(d[1]), "+f"(d[2]), "+f"(d[3])
        : "r"(a[0]), "r"(a[1]), "r"(a[2]), "r"(a[3]), "r"(b0), "r"(b1));
}
__device__ __forceinline__ void ldmat4(uint32_t* r, uint32_t addr) {
    asm volatile("ldmatrix.sync.aligned.m8n8.x4.shared.b16 {%0,%1,%2,%3}, [%4];"
                 : "=r"(r[0]), "=r"(r[1]), "=r"(r[2]), "=r"(r[3]) : "r"(addr));
}
__device__ __forceinline__ uint32_t pack2h(__half lo, __half hi) {
    uint16_t l = *(uint16_t*)&lo, h = *(uint16_t*)&hi;
    return ((uint32_t)h << 16) | l;
}
__device__ __forceinline__ float fast_sigmoid(float x) {
    return __fdividef(1.0f, 1.0f + __expf(-x));
}
__device__ __forceinline__ float fast_tanh(float x) {
    return __fdividef(2.0f, 1.0f + __expf(-2.0f * x)) - 1.0f;
}

// ---------------------------------------------------------------------------
// init: h = 0, c = 1 (reference inits c to ones), reset barrier
// ---------------------------------------------------------------------------
__global__ void k_init_state() {
    int i = blockIdx.x * blockDim.x + threadIdx.x;
    if (i < BATCH * UNITS) {
        g_h[i] = __float2half(0.0f);
        g_c[i] = 1.0f;
    }
    if (i == 0) { g_bar_count = 0; g_bar_release = 0; }
}

// ---------------------------------------------------------------------------
// prep: split data into fp16 hi/lo (coalesced) — xproj path
// ---------------------------------------------------------------------------
__global__ void __launch_bounds__(256) k_prep_data(const float* __restrict__ data) {
    size_t i = (size_t)blockIdx.x * 256 + threadIdx.x;
    float x = data[i];
    __half hi = __float2half(x);
    g_x_hi[i] = hi;
    g_x_lo[i] = __float2half(x - __half2float(hi));
}

// ---------------------------------------------------------------------------
// prep: Wh -> fp16 fragment pairs (R13 layout, validated)
// ---------------------------------------------------------------------------
__global__ void __launch_bounds__(256) k_prep_frag(const float* __restrict__ Wh) {
    uint32_t q = blockIdx.x * 256 + threadIdx.x;   // 0 .. 2^20-1
    int lane = q & 31;
    int ks   = (q >> 5) & 7;
    int ntl  = (q >> 8) & 1;
    int w    = (q >> 9) & 7;
    int nt0  = (q >> 12) & 31;
    int s    = (q >> 17) & 7;

    int col = nt0 * 128 + w * 16 + ntl * 8 + (lane >> 2);
    int k   = s * KSL + ks * 16 + 2 * (lane & 3);

    float x0 = __ldg(&Wh[(size_t)k * GDIM + col]);
    float x1 = __ldg(&Wh[(size_t)(k + 1) * GDIM + col]);
    float x2 = __ldg(&Wh[(size_t)(k + 8) * GDIM + col]);
    float x3 = __ldg(&Wh[(size_t)(k + 9) * GDIM + col]);

    uint2 v;
    v.x = pack2h(__float2half(x0), __float2half(x1));
    v.y = pack2h(__float2half(x2), __float2half(x3));
    g_wfrag2[q] = v;
}

// ---------------------------------------------------------------------------
// prep: Wx -> fp16 fragment pairs (same index map as before, uint2 now)
// ---------------------------------------------------------------------------
__global__ void __launch_bounds__(256) k_prep_wx(const float* __restrict__ Wx) {
    uint32_t q = blockIdx.x * 256 + threadIdx.x;   // 0 .. 2^19-1
    int lane = q & 31;
    int ks   = (q >> 5) & 31;
    int nf   = (q >> 10) & 7;
    int wn   = (q >> 13) & 1;
    int nt0  = (q >> 14) & 31;

    int col = nt0 * 128 + wn * 64 + nf * 8 + (lane >> 2);
    int k   = ks * 16 + 2 * (lane & 3);

    float x0 = __ldg(&Wx[(size_t)k * GDIM + col]);
    float x1 = __ldg(&Wx[(size_t)(k + 1) * GDIM + col]);
    float x2 = __ldg(&Wx[(size_t)(k + 8) * GDIM + col]);
    float x3 = __ldg(&Wx[(size_t)(k + 9) * GDIM + col]);

    uint2 v;
    v.x = pack2h(__float2half(x0), __float2half(x1));
    v.y = pack2h(__float2half(x2), __float2half(x3));
    g_wxfrag2[q] = v;
}

// ---------------------------------------------------------------------------
// x-projection on tensor cores, fp16 2-term: (x_hi + x_lo) @ Wx_fp16.
// Block tile 128m x 128n, 8 warps (4m x 2n). A staged in SMEM + ldmatrix;
// B from fp16 fragment-packed global (L2-resident).
// ---------------------------------------------------------------------------
__global__ void __launch_bounds__(256, 2) k_xproj_mma(const float* __restrict__ bias,
                                                      float* __restrict__ dummy) {
    __shared__ uint32_t sh[2][128][PX];

    int tid = threadIdx.x;
    int w = tid >> 5, lane = tid & 31;
    int wn = w & 1, wm = w >> 1;
    int nt0 = blockIdx.x;
    int mt0 = blockIdx.y;
    int n0 = nt0 * 128;
    size_t m0 = (size_t)mt0 * 128;

    const uint32_t* xh = (const uint32_t*)g_x_hi;   // 256 u32 words/row
    const uint32_t* xl = (const uint32_t*)g_x_lo;
    const uint2* wbx = g_wxfrag2 + ((size_t)(nt0 * 2 + wn) * 8) * 1024;

    float acc[2][8][4];
#pragma unroll
    for (int mf = 0; mf < 2; mf++)
#pragma unroll
        for (int nf = 0; nf < 8; nf++)
#pragma unroll
            for (int e = 0; e < 4; e++) acc[mf][nf][e] = 0.0f;

    uint32_t sb0 = smem_u32(&sh[0][0][0]);
    uint32_t sb1 = smem_u32(&sh[1][0][0]);
    int lrow = lane & 15, lhalf = lane >> 4;

    int srow = tid >> 1, sseg = tid & 1;

#pragma unroll 1
    for (int chunk = 0; chunk < 8; chunk++) {
        {
            const uint4* ph = (const uint4*)(xh + (m0 + srow) * 256 + chunk * 32 + sseg * 16);
            const uint4* pl = (const uint4*)(xl + (m0 + srow) * 256 + chunk * 32 + sseg * 16);
#pragma unroll
            for (int j = 0; j < 4; j++)
                *(uint4*)&sh[0][srow][sseg * 16 + j * 4] = ph[j];
#pragma unroll
            for (int j = 0; j < 4; j++)
                *(uint4*)&sh[1][srow][sseg * 16 + j * 4] = pl[j];
        }
        __syncthreads();

#pragma unroll
        for (int ks4 = 0; ks4 < 4; ks4++) {
            int ks = chunk * 4 + ks4;
            uint2 bv[8];
#pragma unroll
            for (int nf = 0; nf < 8; nf++)
                bv[nf] = wbx[(size_t)nf * 1024 + ks * 32 + lane];
#pragma unroll
            for (int mf = 0; mf < 2; mf++) {
                int row = wm * 32 + mf * 16 + lrow;
                uint32_t off = ((uint32_t)row * PX + ks4 * 8 + lhalf * 4) * 4;
                uint32_t ah[4], al[4];
                ldmat4(ah, sb0 + off);
                ldmat4(al, sb1 + off);
#pragma unroll
                for (int nf = 0; nf < 8; nf++) {
                    mma_f16(acc[mf][nf], ah, bv[nf].x, bv[nf].y);   // x_hi * W
                    mma_f16(acc[mf][nf], al, bv[nf].x, bv[nf].y);   // x_lo * W
                }
            }
        }
        __syncthreads();
    }

    int b  = (int)(m0 >> 9);
    int t0 = (int)(m0 & 511);
    int c2 = (lane & 3) * 2;
#pragma unroll
    for (int nf = 0; nf < 8; nf++) {
        int col = n0 + wn * 64 + nf * 8 + c2;
        float2 bb = *(const float2*)&bias[col];
#pragma unroll
        for (int mf = 0; mf < 2; mf++) {
            int r0 = t0 + wm * 32 + mf * 16 + (lane >> 2);
            float2 v0 = {acc[mf][nf][0] + bb.x, acc[mf][nf][1] + bb.y};
            float2 v1 = {acc[mf][nf][2] + bb.x, acc[mf][nf][3] + bb.y};
            *(float2*)&g_xg[((size_t)r0 * BATCH + b) * GDIM + col] = v0;
            *(float2*)&g_xg[((size_t)(r0 + 8) * BATCH + b) * GDIM + col] = v1;
        }
    }
    (void)dummy;
}

// ---------------------------------------------------------------------------
// Fused LSTM step (R15 verbatim — measured best: fp16 1-term, NS=8,
// dual B streams, fast MUFU gates). 256 blocks x 256 threads, 3 CTAs/SM.
// ---------------------------------------------------------------------------
__global__ void __launch_bounds__(256, 3) k_step(int t, float* __restrict__ out) {
    __shared__ uint32_t sh[BATCH][PITCH];

    int tid = threadIdx.x;
    int w = tid >> 5, lane = tid & 31;
    int bx = blockIdx.x;
    int s   = bx >> 5;
    int nt0 = bx & 31;

    const uint32_t* hh = (const uint32_t*)g_h;
    const uint2* wb = g_wfrag2 + ((((size_t)(s * 32 + nt0)) * 8 + w) * 2) * 256;

    {
        int b = tid >> 3, seg = tid & 7;
        const uint4* ph = (const uint4*)(hh + (size_t)b * 512 + s * 64 + seg * 8);
        uint4 v0 = ph[0], v1 = ph[1];
        *(uint4*)&sh[b][seg * 8]     = v0;
        *(uint4*)&sh[b][seg * 8 + 4] = v1;
    }
    __syncthreads();

    float acc[2][2][4];
#pragma unroll
    for (int m = 0; m < 2; m++)
#pragma unroll
        for (int n = 0; n < 2; n++)
#pragma unroll
            for (int e = 0; e < 4; e++) acc[m][n][e] = 0.0f;

    uint32_t sb0 = smem_u32(&sh[0][0]);
    int lrow = lane & 15, lhalf = lane >> 4;

    uint2 bcur0 = wb[lane];
    uint2 bcur1 = wb[256 + lane];

#pragma unroll
    for (int ks = 0; ks < 8; ks++) {
        uint2 bnxt0, bnxt1;
        if (ks < 7) {
            bnxt0 = wb[(ks + 1) * 32 + lane];
            bnxt1 = wb[256 + (ks + 1) * 32 + lane];
        }
        uint32_t ah[2][4];
#pragma unroll
        for (int m = 0; m < 2; m++) {
            uint32_t off = (((uint32_t)(m * 16 + lrow)) * PITCH
                            + ks * 8 + lhalf * 4) * 4;
            ldmat4(ah[m], sb0 + off);
        }
#pragma unroll
        for (int m = 0; m < 2; m++) {
            mma_f16(acc[m][0], ah[m], bcur0.x, bcur0.y);
            mma_f16(acc[m][1], ah[m], bcur1.x, bcur1.y);
        }
        bcur0 = bnxt0;
        bcur1 = bnxt1;
    }

    {
        int r = lane >> 2, c2 = (lane & 3) * 2;
        float* pp = g_part + ((size_t)s * BATCH) * GDIM;
#pragma unroll
        for (int m = 0; m < 2; m++) {
            int b0 = m * 16 + r;
#pragma unroll
            for (int n = 0; n < 2; n++) {
                int col = nt0 * 128 + w * 16 + n * 8 + c2;
                float2 v0 = {acc[m][n][0], acc[m][n][1]};
                float2 v1 = {acc[m][n][2], acc[m][n][3]};
                *(float2*)&pp[(size_t)b0 * GDIM + col] = v0;
                *(float2*)&pp[(size_t)(b0 + 8) * GDIM + col] = v1;
            }
        }
    }

    int pidx = bx * 128 + (tid & 127);
    int pb = pidx >> 10;
    int pu = pidx & 1023;
    const float* xg = g_xg + ((size_t)t * BATCH + pb) * GDIM;
    float ai = 0.f, af = 0.f, ag = 0.f, ao = 0.f;
    if (tid < 128) {
        ai = xg[pu];
        af = xg[UNITS + pu];
        ag = xg[2 * UNITS + pu];
        ao = xg[3 * UNITS + pu];
    }

    __syncthreads();
    if (tid == 0) {
        unsigned int old = bar_arrive_add(&g_bar_count);
        if (old == NBLK - 1) {
            g_bar_count = 0;
            st_release(&g_bar_release, (unsigned int)(t + 1));
        } else {
            while (ld_acquire(&g_bar_release) < (unsigned int)(t + 1))
                __nanosleep(32);
        }
    }
    __syncthreads();

    if (tid < 128) {
#pragma unroll
        for (int ss = 0; ss < NS; ss++) {
            const float* p = g_part + ((size_t)ss * BATCH + pb) * GDIM;
            ai += p[pu];
            af += p[UNITS + pu];
            ag += p[2 * UNITS + pu];
            ao += p[3 * UNITS + pu];
        }

        float ig = fast_sigmoid(ai);
        float fg = fast_sigmoid(af);
        float gg = fast_tanh(ag);
        float og = fast_sigmoid(ao);

        int cu = pb * UNITS + pu;
        float c = fg * g_c[cu] + ig * gg;
        g_c[cu] = c;
        float h = og * fast_tanh(c);

        out[((size_t)pb * SEQT + t) * UNITS + pu] = h;
        g_h[cu] = __float2half(h);
    }
}

// ---------------------------------------------------------------------------
// kernel_launch: 517 graph nodes.
// ---------------------------------------------------------------------------
extern "C" void kernel_launch(void* const* d_in, const int* in_sizes, int n_in,
                              void* d_out, int out_size) {
    (void)in_sizes; (void)n_in; (void)out_size;
    const float* data = (const float*)d_in[0];   // [32,512,512]
    const float* Wx   = (const float*)d_in[1];   // [512,4096]
    const float* Wh   = (const float*)d_in[2];   // [1024,4096]
    const float* bias = (const float*)d_in[3];   // [4096]
    float* out = (float*)d_out;                  // [32,512,1024]

    k_init_state<<<(BATCH * UNITS + 255) / 256, 256>>>();
    k_prep_data<<<(int)(((size_t)MROWS * IND) / 256), 256>>>(data);
    k_prep_frag<<<4096, 256>>>(Wh);
    k_prep_wx<<<2048, 256>>>(Wx);
    k_xproj_mma<<<dim3(32, 128), 256>>>(bias, out);

    for (int t = 0; t < SEQT; t++)
        k_step<<<NBLK, 256>>>(t, out);
}